// round 13
// baseline (speedup 1.0000x reference)
#include <cuda_runtime.h>
#include <cuda_fp16.h>
#include <cstdint>

#define D 128
#define NSEG 50000

// ---------------- device scratch ----------------
__device__ __align__(16) float g_segsum[NSEG * D];
__device__ __align__(16) float g_cnt[NSEG];
// transposed weights Wt[n][k] = W[k][n], single fp16, 4 matrices
__device__ __align__(16) __half g_W[4][D * D];

// ---------------- smem layouts (bytes) ----------------
#define SROW 272u
#define SW    0u            // W: 128 rows x 272B = 34816
#define SA    34816u        // A tile
// phi (64-row tiles): A 64x272=17408, stage 64x512=32768
#define PSTAGE 52224u
#define PBIAS  84992u
#define PSEG0  85504u       // 256 B
#define PSEG1  85760u       // 256 B
#define PHI_SMEM 86016u
// rho (128-row tiles): A 128x272=34816
#define RBIAS 69632u        // 3 x 512 B
#define RCNT  71168u        // 512 B
#define RHO_SMEM 71680u

__device__ __forceinline__ uint32_t smem_u32(const void* p) {
    return (uint32_t)__cvta_generic_to_shared(p);
}

#define LDSM_X4(r, addr)                                                      \
    asm volatile("ldmatrix.sync.aligned.m8n8.x4.shared.b16 {%0,%1,%2,%3}, [%4];" \
                 : "=r"((r)[0]), "=r"((r)[1]), "=r"((r)[2]), "=r"((r)[3])     \
                 : "r"(addr))

#define MMA_F16(d, a, b0, b1)                                                 \
    asm volatile("mma.sync.aligned.m16n8k16.row.col.f32.f16.f16.f32 "         \
                 "{%0,%1,%2,%3},{%4,%5,%6,%7},{%8,%9},{%0,%1,%2,%3};"         \
                 : "+f"((d)[0]), "+f"((d)[1]), "+f"((d)[2]), "+f"((d)[3])     \
                 : "r"((a)[0]), "r"((a)[1]), "r"((a)[2]), "r"((a)[3]),        \
                   "r"(b0), "r"(b1))

__device__ __forceinline__ uint32_t pack_h2(float x, float y) {
    __half2 t = __floats2half2_rn(x, y);
    return *(uint32_t*)&t;
}
__device__ __forceinline__ void cp16(uint32_t dst, const void* src, int bytes) {
    asm volatile("cp.async.cg.shared.global [%0], [%1], 16, %2;"
                 :: "r"(dst), "l"(src), "r"(bytes) : "memory");
}
__device__ __forceinline__ void cp_commit() {
    asm volatile("cp.async.commit_group;" ::: "memory");
}
__device__ __forceinline__ void cp_wait0() {
    asm volatile("cp.async.wait_group 0;" ::: "memory");
}

// ---------------------------------------------------------------------------
__global__ void prep_kernel(const float* __restrict__ W0, const float* __restrict__ W1,
                            const float* __restrict__ W2, const float* __restrict__ W3) {
    int i = blockIdx.x * blockDim.x + threadIdx.x;
    if (i >= 4 * D * D) return;
    const float* Ws[4] = {W0, W1, W2, W3};
    int mat = i >> 14;
    int e = i & (D * D - 1);
    int n = e >> 7, k = e & (D - 1);
    g_W[mat][n * D + k] = __float2half_rn(Ws[mat][k * D + n]);
}

__global__ void zero_kernel() {
    int i = blockIdx.x * blockDim.x + threadIdx.x;
    float4 z = make_float4(0.f, 0.f, 0.f, 0.f);
    if (i < NSEG * D / 4) ((float4*)g_segsum)[i] = z;
    if (i < NSEG / 4) ((float4*)g_cnt)[i] = z;
}

// ---------------------------------------------------------------------------
template <int NTHR>
__device__ __forceinline__ void load_W(char* smem, const __half* __restrict__ W,
                                       int tid) {
    for (int idx = tid; idx < 128 * 16; idx += NTHR) {
        int r = idx >> 4, ch = idx & 15;
        *(uint4*)(smem + SW + (uint32_t)r * SROW + (uint32_t)ch * 16) =
            *(const uint4*)(W + r * D + ch * 8);
    }
}

// ======== fp16 1-term, 16x32 warp tile, pipelined ========
__device__ __forceinline__ void gemm_pass1_16(uint32_t aBase, uint32_t bBase,
                                              float (*acc)[4]) {
    uint32_t A0[4], W0[4], W1[4];
    LDSM_X4(A0, aBase);
    LDSM_X4(W0, bBase);
    LDSM_X4(W1, bBase + 16u * SROW);
#pragma unroll
    for (int k = 0; k < 8; k++) {
        uint32_t A0n[4], W0n[4], W1n[4];
        if (k < 7) {
            LDSM_X4(A0n, aBase + 32);
            LDSM_X4(W0n, bBase + 32);
            LDSM_X4(W1n, bBase + 16u * SROW + 32);
        }
        MMA_F16(acc[0], A0, W0[0], W0[1]);
        MMA_F16(acc[1], A0, W0[2], W0[3]);
        MMA_F16(acc[2], A0, W1[0], W1[1]);
        MMA_F16(acc[3], A0, W1[2], W1[3]);
        if (k < 7) {
#pragma unroll
            for (int i = 0; i < 4; i++) {
                A0[i] = A0n[i]; W0[i] = W0n[i]; W1[i] = W1n[i];
            }
            aBase += 32; bBase += 32;
        }
    }
}

// rho fragments (+bias, opt relu, opt zero-empty) back to A smem as fp16
__device__ __forceinline__ void frag_store_A(char* smem, float (*acc)[4],
                                             const float* bias, const float* sCnt,
                                             bool relu, bool zeroE,
                                             int wm, int wn, int lane) {
    const int grp = lane >> 2, qp = lane & 3;
    const int rA = wm * 16 + grp;
    bool z0 = zeroE && (sCnt[rA] <= 0.f);
    bool z1 = zeroE && (sCnt[rA + 8] <= 0.f);
#pragma unroll
    for (int nt = 0; nt < 4; nt++) {
        int c = wn * 32 + nt * 8 + qp * 2;
        float b0 = bias[c], b1 = bias[c + 1];
        float x0 = acc[nt][0] + b0, y0 = acc[nt][1] + b1;
        float x1 = acc[nt][2] + b0, y1 = acc[nt][3] + b1;
        if (relu) {
            x0 = fmaxf(x0, 0.f); y0 = fmaxf(y0, 0.f);
            x1 = fmaxf(x1, 0.f); y1 = fmaxf(y1, 0.f);
        }
        if (z0) { x0 = 0.f; y0 = 0.f; }
        if (z1) { x1 = 0.f; y1 = 0.f; }
        uint32_t o0 = (uint32_t)rA * SROW + (uint32_t)c * 2;
        uint32_t o1 = (uint32_t)(rA + 8) * SROW + (uint32_t)c * 2;
        *(uint32_t*)(smem + SA + o0) = pack_h2(x0, y0);
        *(uint32_t*)(smem + SA + o1) = pack_h2(x1, y1);
    }
}

// ---------------------------------------------------------------------------
// PERSISTENT phi kernel: 512 threads, 64-row tiles, 2 CTAs/SM.
// Warp layout: wm = wid&3 (16-row strip), wn = wid>>2 (32-col strip).
// ---------------------------------------------------------------------------
__global__ __launch_bounds__(512, 2) void phi_seg_kernel(
    const float* __restrict__ ins, const int* __restrict__ batch,
    const __half* __restrict__ W, const float* __restrict__ bias,
    int nrows, int ntiles)
{
    extern __shared__ __align__(16) char smem[];
    const uint32_t sbase = smem_u32(smem);
    const int tid = threadIdx.x;
    const int wid = tid >> 5, lane = tid & 31;
    const int wm = wid & 3, wn = wid >> 2;

    // prologue prefetch of first tile (64 rows)
    {
        int t = blockIdx.x;
        if (t < ntiles) {
            long long row0 = (long long)t * 64;
            for (int idx = tid; idx < 2048; idx += 512) {
                int r = idx >> 5, c = idx & 31;
                long long gr = row0 + r;
                cp16(sbase + PSTAGE + (uint32_t)idx * 16u,
                     ins + gr * D + c * 4, (gr < nrows) ? 16 : 0);
            }
            if (tid < 16) {
                long long r0 = row0 + tid * 4;
                long long rem = (long long)nrows - r0;
                int sz = rem >= 4 ? 16 : (rem > 0 ? (int)rem * 4 : 0);
                cp16(sbase + PSEG0 + (uint32_t)tid * 16u, batch + r0, sz);
            }
        }
        cp_commit();
    }
    load_W<512>(smem, W, tid);
    if (tid < D) ((float*)(smem + PBIAS))[tid] = bias[tid];

    const uint32_t aRow = (uint32_t)(wm * 16 + (lane & 15));
    const uint32_t aColB = (uint32_t)((lane >> 4) * 16);
    const uint32_t aBase0 = sbase + SA + aRow * SROW + aColB;
    const uint32_t bRow = (uint32_t)((lane & 7) + ((lane & 16) ? 8 : 0));
    const uint32_t bColB = (uint32_t)(((lane & 8) ? 8 : 0) * 2);
    const uint32_t bBase0 = sbase + SW + (bRow + (uint32_t)wn * 32u) * SROW + bColB;

    int buf = 0;
    for (int t = blockIdx.x; t < ntiles; t += gridDim.x) {
        cp_wait0();
        __syncthreads();
        // convert staged fp32 -> fp16
        for (int idx = tid; idx < 2048; idx += 512) {
            int r = idx >> 5, c4 = idx & 31;
            float4 v = *(const float4*)(smem + PSTAGE + (uint32_t)r * 512u + (uint32_t)c4 * 16u);
            uint32_t off = (uint32_t)r * SROW + (uint32_t)c4 * 8;
            *(uint2*)(smem + SA + off) = make_uint2(pack_h2(v.x, v.y), pack_h2(v.z, v.w));
        }
        __syncthreads();   // stage free -> prefetch next tile
        {
            int nt_ = t + gridDim.x;
            if (nt_ < ntiles) {
                long long row0n = (long long)nt_ * 64;
                for (int idx = tid; idx < 2048; idx += 512) {
                    int r = idx >> 5, c = idx & 31;
                    long long gr = row0n + r;
                    cp16(sbase + PSTAGE + (uint32_t)idx * 16u,
                         ins + gr * D + c * 4, (gr < nrows) ? 16 : 0);
                }
                if (tid < 16) {
                    long long r0 = row0n + tid * 4;
                    long long rem = (long long)nrows - r0;
                    int sz = rem >= 4 ? 16 : (rem > 0 ? (int)rem * 4 : 0);
                    cp16(sbase + (buf ? PSEG0 : PSEG1) + (uint32_t)tid * 16u,
                         batch + r0, sz);
                }
            }
            cp_commit();
        }

        float acc[4][4];
#pragma unroll
        for (int i = 0; i < 4; i++)
#pragma unroll
            for (int j = 0; j < 4; j++) acc[i][j] = 0.f;
        gemm_pass1_16(aBase0, bBase0, acc);
        __syncthreads();   // A reads done before epilogue overwrites

        // h = relu(acc + b) stored fp16 into SA
        const float* sB = (const float*)(smem + PBIAS);
        {
            const int grp = lane >> 2, qp = lane & 3;
            const int rA = wm * 16 + grp;
#pragma unroll
            for (int nt = 0; nt < 4; nt++) {
                int c = wn * 32 + nt * 8 + qp * 2;
                float b0 = sB[c], b1 = sB[c + 1];
                *(uint32_t*)(smem + SA + (uint32_t)rA * SROW + (uint32_t)c * 2) =
                    pack_h2(fmaxf(acc[nt][0] + b0, 0.f), fmaxf(acc[nt][1] + b1, 0.f));
                *(uint32_t*)(smem + SA + (uint32_t)(rA + 8) * SROW + (uint32_t)c * 2) =
                    pack_h2(fmaxf(acc[nt][2] + b0, 0.f), fmaxf(acc[nt][3] + b1, 0.f));
            }
        }
        __syncthreads();

        // segment reduce: 16 groups x 4 rows; thread owns 4 cols -> float4 atomics
        const int* sSeg = (const int*)(smem + (buf ? PSEG1 : PSEG0));
        const int row0 = t * 64;
        const int col4 = tid & 31;
        const int rbeg = (tid >> 5) * 4;
        float4 hv[4];
#pragma unroll
        for (int r = 0; r < 4; r++) {
            uint2 u = *(const uint2*)(smem + SA + (uint32_t)(rbeg + r) * SROW +
                                      (uint32_t)col4 * 8);
            __half2 p0 = *(__half2*)&u.x, p1 = *(__half2*)&u.y;
            float2 f0 = __half22float2(p0), f1 = __half22float2(p1);
            hv[r] = make_float4(f0.x, f0.y, f1.x, f1.y);
        }
        int cur = (row0 + rbeg < nrows) ? sSeg[rbeg] : -1;
        float4 run = make_float4(0.f, 0.f, 0.f, 0.f);
        float cnt = 0.f;
#pragma unroll
        for (int r = 0; r < 4; r++) {
            int s = (row0 + rbeg + r < nrows) ? sSeg[rbeg + r] : -1;
            if (s != cur) {
                if (cur >= 0) {
                    atomicAdd((float4*)(g_segsum + (size_t)cur * D + col4 * 4), run);
                    if (col4 == 0) atomicAdd(&g_cnt[cur], cnt);
                }
                cur = s;
                run = make_float4(0.f, 0.f, 0.f, 0.f);
                cnt = 0.f;
            }
            run.x += hv[r].x; run.y += hv[r].y;
            run.z += hv[r].z; run.w += hv[r].w;
            cnt += 1.f;
        }
        if (cur >= 0) {
            atomicAdd((float4*)(g_segsum + (size_t)cur * D + col4 * 4), run);
            if (col4 == 0) atomicAdd(&g_cnt[cur], cnt);
        }
        __syncthreads();   // SA reads done before next convert overwrites
        buf ^= 1;
    }
}

// ---------------------------------------------------------------------------
// fused small path (1024 threads, 128-row tiles, fp16 1-term) — unchanged R12
// ---------------------------------------------------------------------------
__global__ __launch_bounds__(1024, 1) void rho_fused_kernel(
    const __half* __restrict__ W2, const __half* __restrict__ R1,
    const __half* __restrict__ R2,
    const float* __restrict__ b2, const float* __restrict__ rb1,
    const float* __restrict__ rb2, float* __restrict__ outp, int nrows)
{
    extern __shared__ __align__(16) char smem[];
    const uint32_t sbase = smem_u32(smem);
    const int tid = threadIdx.x;
    const int wid = tid >> 5, lane = tid & 31;
    const int wm = wid & 7, wn = wid >> 3;
    const int row0 = blockIdx.x * 128;

    float* sB = (float*)(smem + RBIAS);
    float* sCnt = (float*)(smem + RCNT);
    if (tid < D) {
        sB[tid] = b2[tid];
        sB[128 + tid] = rb1[tid];
        sB[256 + tid] = rb2[tid];
    }
    if (tid < 128) {
        int gr = row0 + tid;
        sCnt[tid] = (gr < nrows) ? g_cnt[gr] : 0.f;
    }
    load_W<1024>(smem, W2, tid);
    __syncthreads();

    for (int idx = tid; idx < 128 * 32; idx += 1024) {
        int r = idx >> 5, c4 = idx & 31;
        float4 v = make_float4(0.f, 0.f, 0.f, 0.f);
        int gr = row0 + r;
        if (gr < nrows) {
            v = *(const float4*)(g_segsum + (size_t)gr * D + c4 * 4);
            float s = 1.f / fmaxf(sCnt[r], 1.f);
            v.x *= s; v.y *= s; v.z *= s; v.w *= s;
        }
        uint32_t off = (uint32_t)r * SROW + (uint32_t)c4 * 8;
        *(uint2*)(smem + SA + off) = make_uint2(pack_h2(v.x, v.y), pack_h2(v.z, v.w));
    }
    __syncthreads();

    const uint32_t aRow = (uint32_t)(wm * 16 + (lane & 15));
    const uint32_t aColB = (uint32_t)((lane >> 4) * 16);
    const uint32_t aBase0 = sbase + SA + aRow * SROW + aColB;
    const uint32_t bRow = (uint32_t)((lane & 7) + ((lane & 16) ? 8 : 0));
    const uint32_t bColB = (uint32_t)(((lane & 8) ? 8 : 0) * 2);
    const uint32_t bBase0 = sbase + SW + (bRow + (uint32_t)wn * 32u) * SROW + bColB;

    float acc[4][4];
#pragma unroll
    for (int i = 0; i < 4; i++)
#pragma unroll
        for (int j = 0; j < 4; j++) acc[i][j] = 0.f;
    gemm_pass1_16(aBase0, bBase0, acc);
    __syncthreads();
    frag_store_A((char*)smem, acc, sB, sCnt, false, true, wm, wn, lane);
    load_W<1024>((char*)smem, R1, tid);
    __syncthreads();

#pragma unroll
    for (int i = 0; i < 4; i++)
#pragma unroll
        for (int j = 0; j < 4; j++) acc[i][j] = 0.f;
    gemm_pass1_16(aBase0, bBase0, acc);
    __syncthreads();
    frag_store_A((char*)smem, acc, sB + 128, sCnt, true, false, wm, wn, lane);
    load_W<1024>((char*)smem, R2, tid);
    __syncthreads();

#pragma unroll
    for (int i = 0; i < 4; i++)
#pragma unroll
        for (int j = 0; j < 4; j++) acc[i][j] = 0.f;
    gemm_pass1_16(aBase0, bBase0, acc);
    {
        const int grp = lane >> 2, qp = lane & 3;
        const int rA = wm * 16 + grp;
        int gr0 = row0 + rA, gr1 = row0 + rA + 8;
#pragma unroll
        for (int nt = 0; nt < 4; nt++) {
            int c = wn * 32 + nt * 8 + qp * 2;
            float b0 = sB[256 + c], b1 = sB[256 + c + 1];
            if (gr0 < nrows)
                *(float2*)(outp + (size_t)gr0 * D + c) =
                    make_float2(acc[nt][0] + b0, acc[nt][1] + b1);
            if (gr1 < nrows)
                *(float2*)(outp + (size_t)gr1 * D + c) =
                    make_float2(acc[nt][2] + b0, acc[nt][3] + b1);
        }
    }
}

// ---------------------------------------------------------------------------
extern "C" void kernel_launch(void* const* d_in, const int* in_sizes, int n_in,
                              void* d_out, int out_size)
{
    const float* ins    = (const float*)d_in[0];
    const int*   batch  = (const int*)d_in[1];
    const float* phi_W1 = (const float*)d_in[3];
    const float* phi_b1 = (const float*)d_in[4];
    const float* phi_W2 = (const float*)d_in[5];
    const float* phi_b2 = (const float*)d_in[6];
    const float* rho_W1 = (const float*)d_in[7];
    const float* rho_b1 = (const float*)d_in[8];
    const float* rho_W2 = (const float*)d_in[9];
    const float* rho_b2 = (const float*)d_in[10];
    float* out = (float*)d_out;

    const int N = in_sizes[0] / D;
    const int ntiles = (N + 63) / 64;

    cudaFuncSetAttribute(phi_seg_kernel, cudaFuncAttributeMaxDynamicSharedMemorySize, PHI_SMEM);
    cudaFuncSetAttribute(rho_fused_kernel, cudaFuncAttributeMaxDynamicSharedMemorySize, RHO_SMEM);

    void* p_w = nullptr;
    cudaGetSymbolAddress(&p_w, g_W);
    const __half* W = (const __half*)p_w;

    int zgrid = (NSEG * D / 4 + 255) / 256;
    zero_kernel<<<zgrid, 256>>>();
    prep_kernel<<<(4 * D * D + 255) / 256, 256>>>(phi_W1, phi_W2, rho_W1, rho_W2);

    int gphi = 296;                 // 2 persistent CTAs per SM
    if (gphi > ntiles) gphi = ntiles;
    phi_seg_kernel<<<gphi, 512, PHI_SMEM>>>(ins, batch,
        W + 0 * D * D, phi_b1, N, ntiles);

    int g2 = (NSEG + 127) / 128;
    rho_fused_kernel<<<g2, 1024, RHO_SMEM>>>(
        W + 1 * D * D, W + 2 * D * D, W + 3 * D * D,
        phi_b2, rho_b1, rho_b2, out, NSEG);
}

// round 14
// speedup vs baseline: 1.1316x; 1.1316x over previous
#include <cuda_runtime.h>
#include <cuda_fp16.h>
#include <cstdint>

#define D 128
#define NSEG 50000

// ---------------- device scratch ----------------
__device__ __align__(16) float g_segsum[NSEG * D];
__device__ __align__(16) float g_cnt[NSEG];
// transposed weights Wt[n][k] = W[k][n], single fp16, 4 matrices
__device__ __align__(16) __half g_W[4][D * D];

// ---------------- smem layouts (bytes) ----------------
#define SROW 272u
#define SW    0u            // W: 128 rows x 272B = 34816
#define SA    34816u        // A: 128 rows x 272B = 34816
// phi extras (no staging buffer -> 2 CTAs/SM)
#define PBIAS 69632u        // 512 B
#define PSEG  70144u        // 512 B
#define PHI_SMEM 70656u
// rho extras
#define RBIAS 69632u        // 3 x 512 B
#define RCNT  71168u        // 512 B
#define RHO_SMEM 71680u

__device__ __forceinline__ uint32_t smem_u32(const void* p) {
    return (uint32_t)__cvta_generic_to_shared(p);
}

#define LDSM_X4(r, addr)                                                      \
    asm volatile("ldmatrix.sync.aligned.m8n8.x4.shared.b16 {%0,%1,%2,%3}, [%4];" \
                 : "=r"((r)[0]), "=r"((r)[1]), "=r"((r)[2]), "=r"((r)[3])     \
                 : "r"(addr))

#define MMA_F16(d, a, b0, b1)                                                 \
    asm volatile("mma.sync.aligned.m16n8k16.row.col.f32.f16.f16.f32 "         \
                 "{%0,%1,%2,%3},{%4,%5,%6,%7},{%8,%9},{%0,%1,%2,%3};"         \
                 : "+f"((d)[0]), "+f"((d)[1]), "+f"((d)[2]), "+f"((d)[3])     \
                 : "r"((a)[0]), "r"((a)[1]), "r"((a)[2]), "r"((a)[3]),        \
                   "r"(b0), "r"(b1))

__device__ __forceinline__ uint32_t pack_h2(float x, float y) {
    __half2 t = __floats2half2_rn(x, y);
    return *(uint32_t*)&t;
}

// ---------------------------------------------------------------------------
__global__ void prep_kernel(const float* __restrict__ W0, const float* __restrict__ W1,
                            const float* __restrict__ W2, const float* __restrict__ W3) {
    int i = blockIdx.x * blockDim.x + threadIdx.x;
    if (i >= 4 * D * D) return;
    const float* Ws[4] = {W0, W1, W2, W3};
    int mat = i >> 14;
    int e = i & (D * D - 1);
    int n = e >> 7, k = e & (D - 1);
    g_W[mat][n * D + k] = __float2half_rn(Ws[mat][k * D + n]);
}

__global__ void zero_kernel() {
    int i = blockIdx.x * blockDim.x + threadIdx.x;
    float4 z = make_float4(0.f, 0.f, 0.f, 0.f);
    if (i < NSEG * D / 4) ((float4*)g_segsum)[i] = z;
    if (i < NSEG / 4) ((float4*)g_cnt)[i] = z;
}

// ---------------------------------------------------------------------------
template <int NTHR>
__device__ __forceinline__ void load_W(char* smem, const __half* __restrict__ W,
                                       int tid) {
    for (int idx = tid; idx < 128 * 16; idx += NTHR) {
        int r = idx >> 4, ch = idx & 15;
        *(uint4*)(smem + SW + (uint32_t)r * SROW + (uint32_t)ch * 16) =
            *(const uint4*)(W + r * D + ch * 8);
    }
}

// ======== phi: fp16 1-term, 32x32 warp tile; A-only prefetch (reg budget) ===
__device__ __forceinline__ void gemm_pass1_32(uint32_t aBase, uint32_t bBase,
                                              float (*acc)[4][4]) {
    uint32_t A0[4], A1[4];
    LDSM_X4(A0, aBase);
    LDSM_X4(A1, aBase + 16u * SROW);
#pragma unroll
    for (int k = 0; k < 8; k++) {
        uint32_t W0[4], W1[4];
        LDSM_X4(W0, bBase);
        LDSM_X4(W1, bBase + 16u * SROW);
        uint32_t A0n[4], A1n[4];
        if (k < 7) {
            LDSM_X4(A0n, aBase + 32);
            LDSM_X4(A1n, aBase + 16u * SROW + 32);
        }
        MMA_F16(acc[0][0], A0, W0[0], W0[1]);
        MMA_F16(acc[0][1], A0, W0[2], W0[3]);
        MMA_F16(acc[0][2], A0, W1[0], W1[1]);
        MMA_F16(acc[0][3], A0, W1[2], W1[3]);
        MMA_F16(acc[1][0], A1, W0[0], W0[1]);
        MMA_F16(acc[1][1], A1, W0[2], W0[3]);
        MMA_F16(acc[1][2], A1, W1[0], W1[1]);
        MMA_F16(acc[1][3], A1, W1[2], W1[3]);
        if (k < 7) {
#pragma unroll
            for (int i = 0; i < 4; i++) { A0[i] = A0n[i]; A1[i] = A1n[i]; }
            aBase += 32; bBase += 32;
        }
    }
}

// ======== rho: fp16 1-term, 16x32 warp tile, fully pipelined (R12) ========
__device__ __forceinline__ void gemm_pass1_16(uint32_t aBase, uint32_t bBase,
                                              float (*acc)[4]) {
    uint32_t A0[4], W0[4], W1[4];
    LDSM_X4(A0, aBase);
    LDSM_X4(W0, bBase);
    LDSM_X4(W1, bBase + 16u * SROW);
#pragma unroll
    for (int k = 0; k < 8; k++) {
        uint32_t A0n[4], W0n[4], W1n[4];
        if (k < 7) {
            LDSM_X4(A0n, aBase + 32);
            LDSM_X4(W0n, bBase + 32);
            LDSM_X4(W1n, bBase + 16u * SROW + 32);
        }
        MMA_F16(acc[0], A0, W0[0], W0[1]);
        MMA_F16(acc[1], A0, W0[2], W0[3]);
        MMA_F16(acc[2], A0, W1[0], W1[1]);
        MMA_F16(acc[3], A0, W1[2], W1[3]);
        if (k < 7) {
#pragma unroll
            for (int i = 0; i < 4; i++) {
                A0[i] = A0n[i]; W0[i] = W0n[i]; W1[i] = W1n[i];
            }
            aBase += 32; bBase += 32;
        }
    }
}

// rho fragments (+bias, opt relu, opt zero-empty) back to A smem as fp16
__device__ __forceinline__ void frag_store_A(char* smem, float (*acc)[4],
                                             const float* bias, const float* sCnt,
                                             bool relu, bool zeroE,
                                             int wm, int wn, int lane) {
    const int grp = lane >> 2, qp = lane & 3;
    const int rA = wm * 16 + grp;
    bool z0 = zeroE && (sCnt[rA] <= 0.f);
    bool z1 = zeroE && (sCnt[rA + 8] <= 0.f);
#pragma unroll
    for (int nt = 0; nt < 4; nt++) {
        int c = wn * 32 + nt * 8 + qp * 2;
        float b0 = bias[c], b1 = bias[c + 1];
        float x0 = acc[nt][0] + b0, y0 = acc[nt][1] + b1;
        float x1 = acc[nt][2] + b0, y1 = acc[nt][3] + b1;
        if (relu) {
            x0 = fmaxf(x0, 0.f); y0 = fmaxf(y0, 0.f);
            x1 = fmaxf(x1, 0.f); y1 = fmaxf(y1, 0.f);
        }
        if (z0) { x0 = 0.f; y0 = 0.f; }
        if (z1) { x1 = 0.f; y1 = 0.f; }
        uint32_t o0 = (uint32_t)rA * SROW + (uint32_t)c * 2;
        uint32_t o1 = (uint32_t)(rA + 8) * SROW + (uint32_t)c * 2;
        *(uint32_t*)(smem + SA + o0) = pack_h2(x0, y0);
        *(uint32_t*)(smem + SA + o1) = pack_h2(x1, y1);
    }
}

// ---------------------------------------------------------------------------
// PERSISTENT phi kernel: 512 threads, 128-row tiles, 2 CTAs/SM (no staging).
// Per tile: direct LDG->cvt->STS convert, 32x32-tile MMA, relu epi, seg reduce.
// ---------------------------------------------------------------------------
__global__ __launch_bounds__(512, 2) void phi_seg_kernel(
    const float* __restrict__ ins, const int* __restrict__ batch,
    const __half* __restrict__ W, const float* __restrict__ bias,
    int nrows, int ntiles)
{
    extern __shared__ __align__(16) char smem[];
    const uint32_t sbase = smem_u32(smem);
    const int tid = threadIdx.x;
    const int wid = tid >> 5, lane = tid & 31;
    const int wm = wid & 3, wn = wid >> 2;

    load_W<512>(smem, W, tid);
    if (tid < D) ((float*)(smem + PBIAS))[tid] = bias[tid];

    const uint32_t aRow = (uint32_t)(wm * 32 + (lane & 15));
    const uint32_t aColB = (uint32_t)((lane >> 4) * 16);
    const uint32_t aBase0 = sbase + SA + aRow * SROW + aColB;
    const uint32_t bRow = (uint32_t)((lane & 7) + ((lane & 16) ? 8 : 0));
    const uint32_t bColB = (uint32_t)(((lane & 8) ? 8 : 0) * 2);
    const uint32_t bBase0 = sbase + SW + (bRow + (uint32_t)wn * 32u) * SROW + bColB;

    int* sSeg = (int*)(smem + PSEG);

    for (int t = blockIdx.x; t < ntiles; t += gridDim.x) {
        // convert: direct LDG float4 -> fp16 -> STS (8 independent loads/thread)
        const long long row0 = (long long)t * 128;
#pragma unroll
        for (int it = 0; it < 8; it++) {
            int idx = tid + it * 512;
            int r = idx >> 5, c4 = idx & 31;
            long long gr = row0 + r;
            float4 v = make_float4(0.f, 0.f, 0.f, 0.f);
            if (gr < nrows) v = *(const float4*)(ins + gr * D + c4 * 4);
            uint32_t off = (uint32_t)r * SROW + (uint32_t)c4 * 8;
            *(uint2*)(smem + SA + off) = make_uint2(pack_h2(v.x, v.y), pack_h2(v.z, v.w));
        }
        if (tid < 32) {
            long long r0 = row0 + tid * 4;
            int4 s = make_int4(-1, -1, -1, -1);
            if (r0 + 3 < nrows) {
                s = *(const int4*)(batch + r0);
            } else {
                if (r0 + 0 < nrows) s.x = batch[r0 + 0];
                if (r0 + 1 < nrows) s.y = batch[r0 + 1];
                if (r0 + 2 < nrows) s.z = batch[r0 + 2];
                if (r0 + 3 < nrows) s.w = batch[r0 + 3];
            }
            *(int4*)(sSeg + tid * 4) = s;
        }
        __syncthreads();

        float acc[2][4][4];
#pragma unroll
        for (int m = 0; m < 2; m++)
#pragma unroll
            for (int i = 0; i < 4; i++)
#pragma unroll
                for (int j = 0; j < 4; j++) acc[m][i][j] = 0.f;
        gemm_pass1_32(aBase0, bBase0, acc);
        __syncthreads();   // A reads done before epilogue overwrites

        // h = relu(acc + b) stored fp16 into SA
        const float* sB = (const float*)(smem + PBIAS);
        {
            const int grp = lane >> 2, qp = lane & 3;
#pragma unroll
            for (int m = 0; m < 2; m++) {
                const int rA = wm * 32 + m * 16 + grp;
#pragma unroll
                for (int nt = 0; nt < 4; nt++) {
                    int c = wn * 32 + nt * 8 + qp * 2;
                    float b0 = sB[c], b1 = sB[c + 1];
                    *(uint32_t*)(smem + SA + (uint32_t)rA * SROW + (uint32_t)c * 2) =
                        pack_h2(fmaxf(acc[m][nt][0] + b0, 0.f),
                                fmaxf(acc[m][nt][1] + b1, 0.f));
                    *(uint32_t*)(smem + SA + (uint32_t)(rA + 8) * SROW + (uint32_t)c * 2) =
                        pack_h2(fmaxf(acc[m][nt][2] + b0, 0.f),
                                fmaxf(acc[m][nt][3] + b1, 0.f));
                }
            }
        }
        __syncthreads();

        // segment reduce: 16 strips x 8 rows; thread owns 4 cols -> float4 atomics
        const int col4 = tid & 31;
        const int rbeg = (tid >> 5) * 8;
        float4 hv[8];
#pragma unroll
        for (int r = 0; r < 8; r++) {
            uint2 u = *(const uint2*)(smem + SA + (uint32_t)(rbeg + r) * SROW +
                                      (uint32_t)col4 * 8);
            __half2 p0 = *(__half2*)&u.x, p1 = *(__half2*)&u.y;
            float2 f0 = __half22float2(p0), f1 = __half22float2(p1);
            hv[r] = make_float4(f0.x, f0.y, f1.x, f1.y);
        }
        int cur = sSeg[rbeg];
        float4 run = make_float4(0.f, 0.f, 0.f, 0.f);
        float cnt = 0.f;
#pragma unroll
        for (int r = 0; r < 8; r++) {
            int s = sSeg[rbeg + r];
            if (s != cur) {
                if (cur >= 0) {
                    atomicAdd((float4*)(g_segsum + (size_t)cur * D + col4 * 4), run);
                    if (col4 == 0) atomicAdd(&g_cnt[cur], cnt);
                }
                cur = s;
                run = make_float4(0.f, 0.f, 0.f, 0.f);
                cnt = 0.f;
            }
            run.x += hv[r].x; run.y += hv[r].y;
            run.z += hv[r].z; run.w += hv[r].w;
            cnt += 1.f;
        }
        if (cur >= 0) {
            atomicAdd((float4*)(g_segsum + (size_t)cur * D + col4 * 4), run);
            if (col4 == 0) atomicAdd(&g_cnt[cur], cnt);
        }
        __syncthreads();   // SA/sSeg reads done before next convert overwrites
    }
}

// ---------------------------------------------------------------------------
// fused small path (1024 threads, 128-row tiles, fp16 1-term) — R12 unchanged
// ---------------------------------------------------------------------------
__global__ __launch_bounds__(1024, 1) void rho_fused_kernel(
    const __half* __restrict__ W2, const __half* __restrict__ R1,
    const __half* __restrict__ R2,
    const float* __restrict__ b2, const float* __restrict__ rb1,
    const float* __restrict__ rb2, float* __restrict__ outp, int nrows)
{
    extern __shared__ __align__(16) char smem[];
    const uint32_t sbase = smem_u32(smem);
    const int tid = threadIdx.x;
    const int wid = tid >> 5, lane = tid & 31;
    const int wm = wid & 7, wn = wid >> 3;
    const int row0 = blockIdx.x * 128;

    float* sB = (float*)(smem + RBIAS);
    float* sCnt = (float*)(smem + RCNT);
    if (tid < D) {
        sB[tid] = b2[tid];
        sB[128 + tid] = rb1[tid];
        sB[256 + tid] = rb2[tid];
    }
    if (tid < 128) {
        int gr = row0 + tid;
        sCnt[tid] = (gr < nrows) ? g_cnt[gr] : 0.f;
    }
    load_W<1024>(smem, W2, tid);
    __syncthreads();

    for (int idx = tid; idx < 128 * 32; idx += 1024) {
        int r = idx >> 5, c4 = idx & 31;
        float4 v = make_float4(0.f, 0.f, 0.f, 0.f);
        int gr = row0 + r;
        if (gr < nrows) {
            v = *(const float4*)(g_segsum + (size_t)gr * D + c4 * 4);
            float s = 1.f / fmaxf(sCnt[r], 1.f);
            v.x *= s; v.y *= s; v.z *= s; v.w *= s;
        }
        uint32_t off = (uint32_t)r * SROW + (uint32_t)c4 * 8;
        *(uint2*)(smem + SA + off) = make_uint2(pack_h2(v.x, v.y), pack_h2(v.z, v.w));
    }
    __syncthreads();

    const uint32_t aRow = (uint32_t)(wm * 16 + (lane & 15));
    const uint32_t aColB = (uint32_t)((lane >> 4) * 16);
    const uint32_t aBase0 = sbase + SA + aRow * SROW + aColB;
    const uint32_t bRow = (uint32_t)((lane & 7) + ((lane & 16) ? 8 : 0));
    const uint32_t bColB = (uint32_t)(((lane & 8) ? 8 : 0) * 2);
    const uint32_t bBase0 = sbase + SW + (bRow + (uint32_t)wn * 32u) * SROW + bColB;

    float acc[4][4];
#pragma unroll
    for (int i = 0; i < 4; i++)
#pragma unroll
        for (int j = 0; j < 4; j++) acc[i][j] = 0.f;
    gemm_pass1_16(aBase0, bBase0, acc);
    __syncthreads();
    frag_store_A((char*)smem, acc, sB, sCnt, false, true, wm, wn, lane);
    load_W<1024>((char*)smem, R1, tid);
    __syncthreads();

#pragma unroll
    for (int i = 0; i < 4; i++)
#pragma unroll
        for (int j = 0; j < 4; j++) acc[i][j] = 0.f;
    gemm_pass1_16(aBase0, bBase0, acc);
    __syncthreads();
    frag_store_A((char*)smem, acc, sB + 128, sCnt, true, false, wm, wn, lane);
    load_W<1024>((char*)smem, R2, tid);
    __syncthreads();

#pragma unroll
    for (int i = 0; i < 4; i++)
#pragma unroll
        for (int j = 0; j < 4; j++) acc[i][j] = 0.f;
    gemm_pass1_16(aBase0, bBase0, acc);
    {
        const int grp = lane >> 2, qp = lane & 3;
        const int rA = wm * 16 + grp;
        int gr0 = row0 + rA, gr1 = row0 + rA + 8;
#pragma unroll
        for (int nt = 0; nt < 4; nt++) {
            int c = wn * 32 + nt * 8 + qp * 2;
            float b0 = sB[256 + c], b1 = sB[256 + c + 1];
            if (gr0 < nrows)
                *(float2*)(outp + (size_t)gr0 * D + c) =
                    make_float2(acc[nt][0] + b0, acc[nt][1] + b1);
            if (gr1 < nrows)
                *(float2*)(outp + (size_t)gr1 * D + c) =
                    make_float2(acc[nt][2] + b0, acc[nt][3] + b1);
        }
    }
}

// ---------------------------------------------------------------------------
extern "C" void kernel_launch(void* const* d_in, const int* in_sizes, int n_in,
                              void* d_out, int out_size)
{
    const float* ins    = (const float*)d_in[0];
    const int*   batch  = (const int*)d_in[1];
    const float* phi_W1 = (const float*)d_in[3];
    const float* phi_b1 = (const float*)d_in[4];
    const float* phi_W2 = (const float*)d_in[5];
    const float* phi_b2 = (const float*)d_in[6];
    const float* rho_W1 = (const float*)d_in[7];
    const float* rho_b1 = (const float*)d_in[8];
    const float* rho_W2 = (const float*)d_in[9];
    const float* rho_b2 = (const float*)d_in[10];
    float* out = (float*)d_out;

    const int N = in_sizes[0] / D;
    const int ntiles = (N + 127) / 128;

    cudaFuncSetAttribute(phi_seg_kernel, cudaFuncAttributeMaxDynamicSharedMemorySize, PHI_SMEM);
    cudaFuncSetAttribute(rho_fused_kernel, cudaFuncAttributeMaxDynamicSharedMemorySize, RHO_SMEM);

    void* p_w = nullptr;
    cudaGetSymbolAddress(&p_w, g_W);
    const __half* W = (const __half*)p_w;

    int zgrid = (NSEG * D / 4 + 255) / 256;
    zero_kernel<<<zgrid, 256>>>();
    prep_kernel<<<(4 * D * D + 255) / 256, 256>>>(phi_W1, phi_W2, rho_W1, rho_W2);

    int gphi = 296;                 // 2 persistent CTAs per SM
    if (gphi > ntiles) gphi = ntiles;
    phi_seg_kernel<<<gphi, 512, PHI_SMEM>>>(ins, batch,
        W + 0 * D * D, phi_b1, N, ntiles);

    int g2 = (NSEG + 127) / 128;
    rho_fused_kernel<<<g2, 1024, RHO_SMEM>>>(
        W + 1 * D * D, W + 2 * D * D, W + 3 * D * D,
        phi_b2, rho_b1, rho_b2, out, NSEG);
}

// round 15
// speedup vs baseline: 1.1742x; 1.0377x over previous
#include <cuda_runtime.h>
#include <cuda_fp16.h>
#include <cstdint>

#define D 128
#define NSEG 50000

// ---------------- device scratch ----------------
__device__ __align__(16) float g_segsum[NSEG * D];
__device__ __align__(16) float g_cnt[NSEG];
// transposed weights Wt[n][k] = W[k][n], single fp16, 4 matrices
__device__ __align__(16) __half g_W[4][D * D];

// ---------------- smem layouts (bytes) ----------------
#define SROW 272u
#define SW    0u            // W: 128 rows x 272B = 34816
#define SA    34816u        // A: 128 rows x 272B = 34816
// phi extras
#define PBIAS 69632u        // 512 B
#define PSEG  70144u        // 512 B
#define PHI_SMEM 70656u
// rho extras
#define RBIAS 69632u        // 3 x 512 B
#define RCNT  71168u        // 512 B
#define RHO_SMEM 71680u

__device__ __forceinline__ uint32_t smem_u32(const void* p) {
    return (uint32_t)__cvta_generic_to_shared(p);
}

#define LDSM_X4(r, addr)                                                      \
    asm volatile("ldmatrix.sync.aligned.m8n8.x4.shared.b16 {%0,%1,%2,%3}, [%4];" \
                 : "=r"((r)[0]), "=r"((r)[1]), "=r"((r)[2]), "=r"((r)[3])     \
                 : "r"(addr))

#define MMA_F16(d, a, b0, b1)                                                 \
    asm volatile("mma.sync.aligned.m16n8k16.row.col.f32.f16.f16.f32 "         \
                 "{%0,%1,%2,%3},{%4,%5,%6,%7},{%8,%9},{%0,%1,%2,%3};"         \
                 : "+f"((d)[0]), "+f"((d)[1]), "+f"((d)[2]), "+f"((d)[3])     \
                 : "r"((a)[0]), "r"((a)[1]), "r"((a)[2]), "r"((a)[3]),        \
                   "r"(b0), "r"(b1))

__device__ __forceinline__ uint32_t pack_h2(float x, float y) {
    __half2 t = __floats2half2_rn(x, y);
    return *(uint32_t*)&t;
}

// ---------------------------------------------------------------------------
// merged zero + weight transpose/convert (one launch)
__global__ void prep_zero_kernel(const float* __restrict__ W0,
                                 const float* __restrict__ W1,
                                 const float* __restrict__ W2,
                                 const float* __restrict__ W3) {
    int i = blockIdx.x * blockDim.x + threadIdx.x;
    float4 z = make_float4(0.f, 0.f, 0.f, 0.f);
    if (i < NSEG * D / 4) ((float4*)g_segsum)[i] = z;
    if (i < NSEG / 4) ((float4*)g_cnt)[i] = z;
    if (i < 4 * D * D) {
        const float* Ws[4] = {W0, W1, W2, W3};
        int mat = i >> 14;
        int e = i & (D * D - 1);
        int n = e >> 7, k = e & (D - 1);
        g_W[mat][n * D + k] = __float2half_rn(Ws[mat][k * D + n]);
    }
}

// ---------------------------------------------------------------------------
template <int NTHR>
__device__ __forceinline__ void load_W(char* smem, const __half* __restrict__ W,
                                       int tid) {
    for (int idx = tid; idx < 128 * 16; idx += NTHR) {
        int r = idx >> 4, ch = idx & 15;
        *(uint4*)(smem + SW + (uint32_t)r * SROW + (uint32_t)ch * 16) =
            *(const uint4*)(W + r * D + ch * 8);
    }
}

// ======== fp16 1-term, 32x32 warp tile; A-only prefetch (64-reg budget) ====
__device__ __forceinline__ void gemm_pass1_32(uint32_t aBase, uint32_t bBase,
                                              float (*acc)[4][4]) {
    uint32_t A0[4], A1[4];
    LDSM_X4(A0, aBase);
    LDSM_X4(A1, aBase + 16u * SROW);
#pragma unroll
    for (int k = 0; k < 8; k++) {
        uint32_t W0[4], W1[4];
        LDSM_X4(W0, bBase);
        LDSM_X4(W1, bBase + 16u * SROW);
        uint32_t A0n[4], A1n[4];
        if (k < 7) {
            LDSM_X4(A0n, aBase + 32);
            LDSM_X4(A1n, aBase + 16u * SROW + 32);
        }
        MMA_F16(acc[0][0], A0, W0[0], W0[1]);
        MMA_F16(acc[0][1], A0, W0[2], W0[3]);
        MMA_F16(acc[0][2], A0, W1[0], W1[1]);
        MMA_F16(acc[0][3], A0, W1[2], W1[3]);
        MMA_F16(acc[1][0], A1, W0[0], W0[1]);
        MMA_F16(acc[1][1], A1, W0[2], W0[3]);
        MMA_F16(acc[1][2], A1, W1[0], W1[1]);
        MMA_F16(acc[1][3], A1, W1[2], W1[3]);
        if (k < 7) {
#pragma unroll
            for (int i = 0; i < 4; i++) { A0[i] = A0n[i]; A1[i] = A1n[i]; }
            aBase += 32; bBase += 32;
        }
    }
}

// 32x32-tile fragments (+bias, opt relu, opt zero-empty) -> A smem as fp16
__device__ __forceinline__ void frag_store_A32(char* smem, float (*acc)[4][4],
                                               const float* bias, const float* sCnt,
                                               bool relu, bool zeroE,
                                               int wm, int wn, int lane) {
    const int grp = lane >> 2, qp = lane & 3;
#pragma unroll
    for (int m = 0; m < 2; m++) {
        const int rA = wm * 32 + m * 16 + grp;
        bool z0 = zeroE && (sCnt[rA] <= 0.f);
        bool z1 = zeroE && (sCnt[rA + 8] <= 0.f);
#pragma unroll
        for (int nt = 0; nt < 4; nt++) {
            int c = wn * 32 + nt * 8 + qp * 2;
            float b0 = bias[c], b1 = bias[c + 1];
            float x0 = acc[m][nt][0] + b0, y0 = acc[m][nt][1] + b1;
            float x1 = acc[m][nt][2] + b0, y1 = acc[m][nt][3] + b1;
            if (relu) {
                x0 = fmaxf(x0, 0.f); y0 = fmaxf(y0, 0.f);
                x1 = fmaxf(x1, 0.f); y1 = fmaxf(y1, 0.f);
            }
            if (z0) { x0 = 0.f; y0 = 0.f; }
            if (z1) { x1 = 0.f; y1 = 0.f; }
            uint32_t o0 = (uint32_t)rA * SROW + (uint32_t)c * 2;
            uint32_t o1 = (uint32_t)(rA + 8) * SROW + (uint32_t)c * 2;
            *(uint32_t*)(smem + SA + o0) = pack_h2(x0, y0);
            *(uint32_t*)(smem + SA + o1) = pack_h2(x1, y1);
        }
    }
}

// ---------------------------------------------------------------------------
// PERSISTENT phi kernel: 512 threads, 128-row tiles, 2 CTAs/SM — R14 winner.
// ---------------------------------------------------------------------------
__global__ __launch_bounds__(512, 2) void phi_seg_kernel(
    const float* __restrict__ ins, const int* __restrict__ batch,
    const __half* __restrict__ W, const float* __restrict__ bias,
    int nrows, int ntiles)
{
    extern __shared__ __align__(16) char smem[];
    const uint32_t sbase = smem_u32(smem);
    const int tid = threadIdx.x;
    const int wid = tid >> 5, lane = tid & 31;
    const int wm = wid & 3, wn = wid >> 2;

    load_W<512>(smem, W, tid);
    if (tid < D) ((float*)(smem + PBIAS))[tid] = bias[tid];

    const uint32_t aRow = (uint32_t)(wm * 32 + (lane & 15));
    const uint32_t aColB = (uint32_t)((lane >> 4) * 16);
    const uint32_t aBase0 = sbase + SA + aRow * SROW + aColB;
    const uint32_t bRow = (uint32_t)((lane & 7) + ((lane & 16) ? 8 : 0));
    const uint32_t bColB = (uint32_t)(((lane & 8) ? 8 : 0) * 2);
    const uint32_t bBase0 = sbase + SW + (bRow + (uint32_t)wn * 32u) * SROW + bColB;

    int* sSeg = (int*)(smem + PSEG);

    for (int t = blockIdx.x; t < ntiles; t += gridDim.x) {
        const long long row0 = (long long)t * 128;
#pragma unroll
        for (int it = 0; it < 8; it++) {
            int idx = tid + it * 512;
            int r = idx >> 5, c4 = idx & 31;
            long long gr = row0 + r;
            float4 v = make_float4(0.f, 0.f, 0.f, 0.f);
            if (gr < nrows) v = *(const float4*)(ins + gr * D + c4 * 4);
            uint32_t off = (uint32_t)r * SROW + (uint32_t)c4 * 8;
            *(uint2*)(smem + SA + off) = make_uint2(pack_h2(v.x, v.y), pack_h2(v.z, v.w));
        }
        if (tid < 32) {
            long long r0 = row0 + tid * 4;
            int4 s = make_int4(-1, -1, -1, -1);
            if (r0 + 3 < nrows) {
                s = *(const int4*)(batch + r0);
            } else {
                if (r0 + 0 < nrows) s.x = batch[r0 + 0];
                if (r0 + 1 < nrows) s.y = batch[r0 + 1];
                if (r0 + 2 < nrows) s.z = batch[r0 + 2];
                if (r0 + 3 < nrows) s.w = batch[r0 + 3];
            }
            *(int4*)(sSeg + tid * 4) = s;
        }
        __syncthreads();

        float acc[2][4][4];
#pragma unroll
        for (int m = 0; m < 2; m++)
#pragma unroll
            for (int i = 0; i < 4; i++)
#pragma unroll
                for (int j = 0; j < 4; j++) acc[m][i][j] = 0.f;
        gemm_pass1_32(aBase0, bBase0, acc);
        __syncthreads();

        // h = relu(acc + b) stored fp16 into SA
        frag_store_A32((char*)smem, acc, (const float*)(smem + PBIAS), nullptr,
                       true, false, wm, wn, lane);
        __syncthreads();

        // segment reduce: 16 strips x 8 rows; thread owns 4 cols -> float4 atomics
        const int col4 = tid & 31;
        const int rbeg = (tid >> 5) * 8;
        float4 hv[8];
#pragma unroll
        for (int r = 0; r < 8; r++) {
            uint2 u = *(const uint2*)(smem + SA + (uint32_t)(rbeg + r) * SROW +
                                      (uint32_t)col4 * 8);
            __half2 p0 = *(__half2*)&u.x, p1 = *(__half2*)&u.y;
            float2 f0 = __half22float2(p0), f1 = __half22float2(p1);
            hv[r] = make_float4(f0.x, f0.y, f1.x, f1.y);
        }
        int cur = sSeg[rbeg];
        float4 run = make_float4(0.f, 0.f, 0.f, 0.f);
        float cnt = 0.f;
#pragma unroll
        for (int r = 0; r < 8; r++) {
            int s = sSeg[rbeg + r];
            if (s != cur) {
                if (cur >= 0) {
                    atomicAdd((float4*)(g_segsum + (size_t)cur * D + col4 * 4), run);
                    if (col4 == 0) atomicAdd(&g_cnt[cur], cnt);
                }
                cur = s;
                run = make_float4(0.f, 0.f, 0.f, 0.f);
                cnt = 0.f;
            }
            run.x += hv[r].x; run.y += hv[r].y;
            run.z += hv[r].z; run.w += hv[r].w;
            cnt += 1.f;
        }
        if (cur >= 0) {
            atomicAdd((float4*)(g_segsum + (size_t)cur * D + col4 * 4), run);
            if (col4 == 0) atomicAdd(&g_cnt[cur], cnt);
        }
        __syncthreads();
    }
}

// ---------------------------------------------------------------------------
// fused small path: 512 threads, 128-row tiles, 32x32 warp tiles, 2 CTAs/SM.
// ---------------------------------------------------------------------------
__global__ __launch_bounds__(512, 2) void rho_fused_kernel(
    const __half* __restrict__ W2, const __half* __restrict__ R1,
    const __half* __restrict__ R2,
    const float* __restrict__ b2, const float* __restrict__ rb1,
    const float* __restrict__ rb2, float* __restrict__ outp, int nrows)
{
    extern __shared__ __align__(16) char smem[];
    const uint32_t sbase = smem_u32(smem);
    const int tid = threadIdx.x;
    const int wid = tid >> 5, lane = tid & 31;
    const int wm = wid & 3, wn = wid >> 2;
    const int row0 = blockIdx.x * 128;

    float* sB = (float*)(smem + RBIAS);
    float* sCnt = (float*)(smem + RCNT);
    if (tid < D) {
        sB[tid] = b2[tid];
        sB[128 + tid] = rb1[tid];
        sB[256 + tid] = rb2[tid];
    }
    if (tid < 128) {
        int gr = row0 + tid;
        sCnt[tid] = (gr < nrows) ? g_cnt[gr] : 0.f;
    }
    load_W<512>(smem, W2, tid);
    __syncthreads();

    // A tile: mean = segsum / max(cnt,1), fp16
    for (int idx = tid; idx < 128 * 32; idx += 512) {
        int r = idx >> 5, c4 = idx & 31;
        float4 v = make_float4(0.f, 0.f, 0.f, 0.f);
        int gr = row0 + r;
        if (gr < nrows) {
            v = *(const float4*)(g_segsum + (size_t)gr * D + c4 * 4);
            float s = 1.f / fmaxf(sCnt[r], 1.f);
            v.x *= s; v.y *= s; v.z *= s; v.w *= s;
        }
        uint32_t off = (uint32_t)r * SROW + (uint32_t)c4 * 8;
        *(uint2*)(smem + SA + off) = make_uint2(pack_h2(v.x, v.y), pack_h2(v.z, v.w));
    }
    __syncthreads();

    const uint32_t aRow = (uint32_t)(wm * 32 + (lane & 15));
    const uint32_t aColB = (uint32_t)((lane >> 4) * 16);
    const uint32_t aBase0 = sbase + SA + aRow * SROW + aColB;
    const uint32_t bRow = (uint32_t)((lane & 7) + ((lane & 16) ? 8 : 0));
    const uint32_t bColB = (uint32_t)(((lane & 8) ? 8 : 0) * 2);
    const uint32_t bBase0 = sbase + SW + (bRow + (uint32_t)wn * 32u) * SROW + bColB;

    float acc[2][4][4];
    // ---- stage 1: u = mean@phiW2 + b2 (zero empty rows) ----
#pragma unroll
    for (int m = 0; m < 2; m++)
#pragma unroll
        for (int i = 0; i < 4; i++)
#pragma unroll
            for (int j = 0; j < 4; j++) acc[m][i][j] = 0.f;
    gemm_pass1_32(aBase0, bBase0, acc);
    __syncthreads();
    frag_store_A32((char*)smem, acc, sB, sCnt, false, true, wm, wn, lane);
    load_W<512>((char*)smem, R1, tid);
    __syncthreads();

    // ---- stage 2: v = relu(u@rhoW1 + rb1) ----
#pragma unroll
    for (int m = 0; m < 2; m++)
#pragma unroll
        for (int i = 0; i < 4; i++)
#pragma unroll
            for (int j = 0; j < 4; j++) acc[m][i][j] = 0.f;
    gemm_pass1_32(aBase0, bBase0, acc);
    __syncthreads();
    frag_store_A32((char*)smem, acc, sB + 128, sCnt, true, false, wm, wn, lane);
    load_W<512>((char*)smem, R2, tid);
    __syncthreads();

    // ---- stage 3: out = v@rhoW2 + rb2 ----
#pragma unroll
    for (int m = 0; m < 2; m++)
#pragma unroll
        for (int i = 0; i < 4; i++)
#pragma unroll
            for (int j = 0; j < 4; j++) acc[m][i][j] = 0.f;
    gemm_pass1_32(aBase0, bBase0, acc);
    {
        const int grp = lane >> 2, qp = lane & 3;
#pragma unroll
        for (int m = 0; m < 2; m++) {
            const int rA = wm * 32 + m * 16 + grp;
            int gr0 = row0 + rA, gr1 = row0 + rA + 8;
#pragma unroll
            for (int nt = 0; nt < 4; nt++) {
                int c = wn * 32 + nt * 8 + qp * 2;
                float b0 = sB[256 + c], b1 = sB[256 + c + 1];
                if (gr0 < nrows)
                    *(float2*)(outp + (size_t)gr0 * D + c) =
                        make_float2(acc[m][nt][0] + b0, acc[m][nt][1] + b1);
                if (gr1 < nrows)
                    *(float2*)(outp + (size_t)gr1 * D + c) =
                        make_float2(acc[m][nt][2] + b0, acc[m][nt][3] + b1);
            }
        }
    }
}

// ---------------------------------------------------------------------------
extern "C" void kernel_launch(void* const* d_in, const int* in_sizes, int n_in,
                              void* d_out, int out_size)
{
    const float* ins    = (const float*)d_in[0];
    const int*   batch  = (const int*)d_in[1];
    const float* phi_W1 = (const float*)d_in[3];
    const float* phi_b1 = (const float*)d_in[4];
    const float* phi_W2 = (const float*)d_in[5];
    const float* phi_b2 = (const float*)d_in[6];
    const float* rho_W1 = (const float*)d_in[7];
    const float* rho_b1 = (const float*)d_in[8];
    const float* rho_W2 = (const float*)d_in[9];
    const float* rho_b2 = (const float*)d_in[10];
    float* out = (float*)d_out;

    const int N = in_sizes[0] / D;
    const int ntiles = (N + 127) / 128;

    cudaFuncSetAttribute(phi_seg_kernel, cudaFuncAttributeMaxDynamicSharedMemorySize, PHI_SMEM);
    cudaFuncSetAttribute(rho_fused_kernel, cudaFuncAttributeMaxDynamicSharedMemorySize, RHO_SMEM);

    void* p_w = nullptr;
    cudaGetSymbolAddress(&p_w, g_W);
    const __half* W = (const __half*)p_w;

    int pzgrid = (NSEG * D / 4 + 255) / 256;   // covers zero (largest range) + prep
    prep_zero_kernel<<<pzgrid, 256>>>(phi_W1, phi_W2, rho_W1, rho_W2);

    int gphi = 296;                 // 2 persistent CTAs per SM
    if (gphi > ntiles) gphi = ntiles;
    phi_seg_kernel<<<gphi, 512, PHI_SMEM>>>(ins, batch,
        W + 0 * D * D, phi_b1, N, ntiles);

    int g2 = (NSEG + 127) / 128;
    rho_fused_kernel<<<g2, 512, RHO_SMEM>>>(
        W + 1 * D * D, W + 2 * D * D, W + 3 * D * D,
        phi_b2, rho_b1, rho_b2, out, NSEG);
}